// round 14
// baseline (speedup 1.0000x reference)
#include <cuda_runtime.h>
#include <cuda_fp16.h>
#include <cstdint>

#define BB 4
#define LL 4096
#define DD 256
#define BL (BB*LL)
#define NB 129          // chunks per batch (128) + overflow bin (t=4096)
#define NBT (BB*NB)

// ---------------- static scratch ----------------
__device__ float g_V[BL*DD];
__device__ float g_uq[DD];
__device__ float g_uk[DD];
__device__ float g_qs[BL];
__device__ float g_ks[BL];
__device__ float g_ksort[BL];
__device__ int   g_ord[BL];
__device__ int   g_t[BL];
__device__ unsigned long long g_tk[BL];   // per-tile sorted packed keys
__device__ float g_chE[BB*NB];
__device__ float g_chEV[BB*NB*DD];
__device__ float g_chV[BB*NB*DD];

__device__ __forceinline__ uint32_t fmap(float f) {
    uint32_t u = __float_as_uint(f);
    return ((int)u < 0) ? ~u : (u | 0x80000000u);
}

// ---------------- uq = Wq^T w, uk = Wk^T w ----------------
__global__ void __launch_bounds__(1024) k_uvec(const float* __restrict__ Wq,
                                               const float* __restrict__ Wk,
                                               const float* __restrict__ w) {
    __shared__ float part[4][DD];
    const float* W = (blockIdx.x == 0) ? Wq : Wk;
    int d = threadIdx.x & 255, ec = threadIdx.x >> 8;
    float s = 0.f;
    #pragma unroll 8
    for (int e = ec * 64; e < ec * 64 + 64; e++)
        s = fmaf(W[e * DD + d], w[e], s);
    part[ec][d] = s;
    __syncthreads();
    if (ec == 0) {
        float r = part[0][d] + part[1][d] + part[2][d] + part[3][d];
        if (blockIdx.x == 0) g_uq[d] = r; else g_uk[d] = r;
    }
}

// ---------------- per-row scalar q/k ----------------
__global__ void __launch_bounds__(256) k_qk(const float* __restrict__ x,
                                            const float* __restrict__ bptr) {
    __shared__ float suq[DD], suk[DD];
    suq[threadIdx.x] = g_uq[threadIdx.x];
    suk[threadIdx.x] = g_uk[threadIdx.x];
    __syncthreads();
    int warp = threadIdx.x >> 5, lane = threadIdx.x & 31;
    float bias = bptr[0];
    #pragma unroll
    for (int r = 0; r < 8; r++) {
        int m = blockIdx.x * 64 + warp * 8 + r;
        const float* xr = x + (size_t)m * DD;
        float4 xa = *(const float4*)&xr[lane * 4];
        float4 xb = *(const float4*)&xr[128 + lane * 4];
        int da = lane * 4, db = 128 + lane * 4;
        float sq = xa.x * suq[da] + xa.y * suq[da+1] + xa.z * suq[da+2] + xa.w * suq[da+3]
                 + xb.x * suq[db] + xb.y * suq[db+1] + xb.z * suq[db+2] + xb.w * suq[db+3];
        float sk = xa.x * suk[da] + xa.y * suk[da+1] + xa.z * suk[da+2] + xa.w * suk[da+3]
                 + xb.x * suk[db] + xb.y * suk[db+1] + xb.z * suk[db+2] + xb.w * suk[db+3];
        #pragma unroll
        for (int o = 16; o; o >>= 1) {
            sq += __shfl_down_sync(0xffffffffu, sq, o);
            sk += __shfl_down_sync(0xffffffffu, sk, o);
        }
        if (lane == 0) { g_qs[m] = sq + bias; g_ks[m] = sk; }
    }
}

// ---------------- V = x @ Wv^T : mma.sync fp16 2-pass split ----------------
#define PITCH 36
__device__ __forceinline__ void mma_fp16(float* d, const uint32_t* a, const uint32_t* b) {
    asm volatile("mma.sync.aligned.m16n8k16.row.col.f32.f16.f16.f32 "
        "{%0,%1,%2,%3}, {%4,%5,%6,%7}, {%8,%9}, {%0,%1,%2,%3};"
        : "+f"(d[0]), "+f"(d[1]), "+f"(d[2]), "+f"(d[3])
        : "r"(a[0]), "r"(a[1]), "r"(a[2]), "r"(a[3]), "r"(b[0]), "r"(b[1]));
}

__global__ void __launch_bounds__(256) k_vgemm(const float* __restrict__ x,
                                               const float* __restrict__ Wv) {
    __shared__ __half sAh[128][PITCH];
    __shared__ __half sBh[128][PITCH], sBl[128][PITCH];
    int tid = threadIdx.x, wid = tid >> 5, lane = tid & 31;
    int g = lane >> 2, t4 = lane & 3;
    int wr = wid >> 2, wc = wid & 3;
    int m0 = blockIdx.x * 128, n0 = blockIdx.y * 128;

    float acc[4][4][4];
    #pragma unroll
    for (int mt = 0; mt < 4; mt++)
        #pragma unroll
        for (int nt = 0; nt < 4; nt++)
            #pragma unroll
            for (int e = 0; e < 4; e++) acc[mt][nt][e] = 0.f;

    for (int k0 = 0; k0 < DD; k0 += 32) {
        #pragma unroll
        for (int p = 0; p < 8; p++) {
            int s = p * 256 + tid;
            int row = (s & 1023) >> 3, kq = s & 7;
            if (s < 1024) {
                float4 v = *(const float4*)&x[(size_t)(m0 + row) * DD + k0 + kq * 4];
                __half2 h0 = __floats2half2_rn(v.x, v.y);
                __half2 h1 = __floats2half2_rn(v.z, v.w);
                *(uint2*)&sAh[row][kq * 4] =
                    make_uint2(*(uint32_t*)&h0, *(uint32_t*)&h1);
            } else {
                float4 v = *(const float4*)&Wv[(size_t)(n0 + row) * DD + k0 + kq * 4];
                __half2 h0 = __floats2half2_rn(v.x, v.y);
                __half2 h1 = __floats2half2_rn(v.z, v.w);
                __half2 l0 = __floats2half2_rn(v.x - __low2float(h0),
                                               v.y - __high2float(h0));
                __half2 l1 = __floats2half2_rn(v.z - __low2float(h1),
                                               v.w - __high2float(h1));
                *(uint2*)&sBh[row][kq * 4] =
                    make_uint2(*(uint32_t*)&h0, *(uint32_t*)&h1);
                *(uint2*)&sBl[row][kq * 4] =
                    make_uint2(*(uint32_t*)&l0, *(uint32_t*)&l1);
            }
        }
        __syncthreads();
        #pragma unroll
        for (int ks = 0; ks < 32; ks += 16) {
            uint32_t ah[4][4], bh[4][2], bl[4][2];
            #pragma unroll
            for (int mt = 0; mt < 4; mt++) {
                int rb = wr * 64 + mt * 16;
                int kc = ks + 2 * t4;
                ah[mt][0] = *(uint32_t*)&sAh[rb + g    ][kc];
                ah[mt][1] = *(uint32_t*)&sAh[rb + g + 8][kc];
                ah[mt][2] = *(uint32_t*)&sAh[rb + g    ][kc + 8];
                ah[mt][3] = *(uint32_t*)&sAh[rb + g + 8][kc + 8];
            }
            #pragma unroll
            for (int nt = 0; nt < 4; nt++) {
                int nb = wc * 32 + nt * 8;
                int kc = ks + 2 * t4;
                bh[nt][0] = *(uint32_t*)&sBh[nb + g][kc];
                bh[nt][1] = *(uint32_t*)&sBh[nb + g][kc + 8];
                bl[nt][0] = *(uint32_t*)&sBl[nb + g][kc];
                bl[nt][1] = *(uint32_t*)&sBl[nb + g][kc + 8];
            }
            #pragma unroll
            for (int mt = 0; mt < 4; mt++)
                #pragma unroll
                for (int nt = 0; nt < 4; nt++) {
                    mma_fp16(acc[mt][nt], ah[mt], bh[nt]);
                    mma_fp16(acc[mt][nt], ah[mt], bl[nt]);
                }
        }
        __syncthreads();
    }
    #pragma unroll
    for (int mt = 0; mt < 4; mt++)
        #pragma unroll
        for (int nt = 0; nt < 4; nt++) {
            int m = m0 + wr * 64 + mt * 16 + g;
            int n = n0 + wc * 32 + nt * 8 + 2 * t4;
            *(float2*)&g_V[(size_t)m * DD + n] =
                make_float2(acc[mt][nt][0], acc[mt][nt][1]);
            *(float2*)&g_V[(size_t)(m + 8) * DD + n] =
                make_float2(acc[mt][nt][2], acc[mt][nt][3]);
        }
}

// ---------------- sort 256-key tiles (bitonic, u64 packed keys) ----------------
__global__ void __launch_bounds__(256) k_tsort() {
    __shared__ unsigned long long sk[256];
    int base = blockIdx.x * 256;
    int tid = threadIdx.x;
    int jloc = (base + tid) & (LL - 1);
    sk[tid] = ((unsigned long long)fmap(g_ks[base + tid]) << 12) | (unsigned)jloc;
    __syncthreads();
    for (int k = 2; k <= 256; k <<= 1) {
        for (int j = k >> 1; j > 0; j >>= 1) {
            int ixj = tid ^ j;
            if (ixj > tid) {
                bool asc = ((tid & k) == 0);
                unsigned long long a = sk[tid], c = sk[ixj];
                if (asc ? (a > c) : (a < c)) { sk[tid] = c; sk[ixj] = a; }
            }
            __syncthreads();
        }
    }
    g_tk[base + tid] = sk[tid];
}

// ---------------- exact lower_bound over 256 sorted unique keys (binary) ----------------
__device__ __forceinline__ int lb256(const unsigned long long* st, unsigned long long key) {
    if (st[255] < key) return 256;
    int pos = 0;
    #pragma unroll
    for (int step = 128; step; step >>= 1)
        if (st[pos + step - 1] < key) pos += step;
    return pos;
}

// ---------------- fused rank + scatter: loop over 16 tiles, double-buffered ----------------
__global__ void __launch_bounds__(128) k_rankscatter() {
    __shared__ unsigned long long buf[2][256];
    int b  = blockIdx.x >> 5;          // 4 batches × 32 j-chunks
    int jc = blockIdx.x & 31;
    int tid = threadIdx.x;
    int j = b * LL + jc * 128 + tid;
    unsigned long long kj = ((unsigned long long)fmap(g_ks[j]) << 12)
                          | (unsigned)(j & (LL - 1));
    unsigned long long qj = ((unsigned long long)fmap(g_qs[j]) << 12);
    // prologue: tile 0
    buf[0][tid]       = g_tk[b * LL + tid];
    buf[0][tid + 128] = g_tk[b * LL + tid + 128];
    int sumk = 0, sumq = 0;
    for (int t = 0; t < 16; t++) {
        unsigned long long r0 = 0, r1 = 0;
        if (t + 1 < 16) {                              // prefetch next tile
            r0 = g_tk[b * LL + (t + 1) * 256 + tid];
            r1 = g_tk[b * LL + (t + 1) * 256 + tid + 128];
        }
        __syncthreads();                               // buf[t&1] stores visible
        const unsigned long long* st = buf[t & 1];
        sumk += lb256(st, kj);
        sumq += lb256(st, qj);
        if (t + 1 < 16) {
            buf[(t + 1) & 1][tid]       = r0;
            buf[(t + 1) & 1][tid + 128] = r1;
        }
    }
    g_ksort[b * LL + sumk] = g_ks[j];
    g_ord  [b * LL + sumk] = j & (LL - 1);
    g_t[j] = sumq;
}

// ---------------- chunk sums (32-element chunks) ----------------
__global__ void __launch_bounds__(256) k_chunksum() {
    int bx = blockIdx.x;
    int b = bx >> 7, c = bx & 127;
    int d = threadIdx.x;
    __shared__ float ev[32];
    __shared__ int   sord[32];
    int base = b * LL + c * 32;
    if (d < 32) {
        float e = expf(-g_ksort[base + d]);
        ev[d] = e;
        sord[d] = g_ord[base + d];
        #pragma unroll
        for (int o = 16; o; o >>= 1) e += __shfl_down_sync(0xffffffffu, e, o);
        if (d == 0) g_chE[b * NB + c] = e;
    }
    __syncthreads();
    float sEV = 0.f, sV = 0.f;
    #pragma unroll 4
    for (int i = 0; i < 32; i++) {
        float v = g_V[(size_t)(b * LL + sord[i]) * DD + d];
        sEV = fmaf(ev[i], v, sEV);
        sV += v;
    }
    g_chEV[(b * NB + c) * DD + d] = sEV;
    g_chV [(b * NB + c) * DD + d] = sV;
}

// ---------------- exclusive scan over chunk sums (+ totals at idx 128) ----------------
__global__ void __launch_bounds__(256) k_chunkscan() {
    int b = blockIdx.x, d = threadIdx.x;
    float runEV = 0.f, runV = 0.f;
    #pragma unroll 8
    for (int c = 0; c < 128; c++) {
        int idx = (b * NB + c) * DD + d;
        float t1 = g_chEV[idx]; g_chEV[idx] = runEV; runEV += t1;
        float t2 = g_chV[idx];  g_chV[idx]  = runV;  runV  += t2;
    }
    g_chEV[(b * NB + 128) * DD + d] = runEV;
    g_chV [(b * NB + 128) * DD + d] = runV;
    if (d == 0) {
        float run = 0.f;
        #pragma unroll 8
        for (int c = 0; c < 128; c++) {
            float t = g_chE[b * NB + c]; g_chE[b * NB + c] = run; run += t;
        }
        g_chE[b * NB + 128] = run;
    }
}

// ---------------- grouped output: one block per (batch, chunk) bin ----------------
__global__ void __launch_bounds__(256) k_gout(float* __restrict__ out) {
    extern __shared__ float dsm[];
    float* pEV = dsm;               // [33][256]
    float* pV  = dsm + 33 * 256;    // [33][256]
    __shared__ float ev[32];
    __shared__ int   sord[32];
    __shared__ float pe[33];
    __shared__ int   slist[4096];
    __shared__ int   scount;
    int gbin = blockIdx.x;
    int b = gbin / NB, c = gbin - b * NB;
    int d = threadIdx.x;
    if (d == 0) scount = 0;
    int csize = (c < 128) ? 32 : 0;
    if (d < 32 && csize) {
        ev[d]   = expf(-g_ksort[b * LL + c * 32 + d]);
        sord[d] = g_ord[b * LL + c * 32 + d];
    }
    __syncthreads();
    // gather this bin's queries from g_t
    #pragma unroll 4
    for (int idx = d; idx < LL; idx += 256) {
        int t = g_t[b * LL + idx];
        if ((t >> 5) == c) slist[atomicAdd(&scount, 1)] = idx;
    }
    __syncthreads();
    int nq = scount;
    if (nq == 0) return;
    // build within-chunk prefixes on top of inter-chunk exclusive base
    pEV[d] = g_chEV[(b * NB + c) * DD + d];
    pV [d] = g_chV [(b * NB + c) * DD + d];
    if (csize) {
        float vr[32];
        #pragma unroll
        for (int i = 0; i < 32; i++)
            vr[i] = g_V[(size_t)(b * LL + sord[i]) * DD + d];
        #pragma unroll
        for (int i = 0; i < 32; i++) {
            pEV[(i + 1) * 256 + d] = fmaf(ev[i], vr[i], pEV[i * 256 + d]);
            pV [(i + 1) * 256 + d] = pV[i * 256 + d] + vr[i];
        }
    }
    if (d == 0) {
        float a = g_chE[b * NB + c];
        pe[0] = a;
        for (int i = 0; i < csize; i++) { a += ev[i]; pe[i + 1] = a; }
    }
    float TVd = g_chV[(b * NB + 128) * DD + d];
    __syncthreads();
    for (int p = 0; p < nq; p++) {
        int ql = slist[p];
        int qi = b * LL + ql;
        int t = g_t[qi];
        int rloc = t - c * 32;
        float E = expf(g_qs[qi]);
        float den = fmaf(E, pe[rloc], (float)(LL - t));
        float num = fmaf(E, pEV[rloc * 256 + d], TVd - pV[rloc * 256 + d]);
        out[(size_t)qi * DD + d] = num / den;
    }
}

// ---------------- launch: fork sort-chain onto a second stream under the GEMM ----------------
extern "C" void kernel_launch(void* const* d_in, const int* in_sizes, int n_in,
                              void* d_out, int out_size) {
    const float* x   = (const float*)d_in[0];
    const float* Wq  = (const float*)d_in[1];
    const float* Wk  = (const float*)d_in[2];
    const float* Wv  = (const float*)d_in[3];
    const float* w   = (const float*)d_in[4];
    const float* bm  = (const float*)d_in[5];
    float* out = (float*)d_out;

    static cudaStream_t s2 = nullptr;
    static cudaEvent_t ev_fork = nullptr, ev_join = nullptr;
    if (!s2) {
        cudaStreamCreateWithFlags(&s2, cudaStreamNonBlocking);
        cudaEventCreateWithFlags(&ev_fork, cudaEventDisableTiming);
        cudaEventCreateWithFlags(&ev_join, cudaEventDisableTiming);
        cudaFuncSetAttribute(k_gout, cudaFuncAttributeMaxDynamicSharedMemorySize,
                             2 * 33 * 256 * (int)sizeof(float));
    }

    // fork
    cudaEventRecord(ev_fork, 0);
    cudaStreamWaitEvent(s2, ev_fork, 0);

    // Leg B (stream s2): scalar/sort/rank chain — latency-bound, hides under GEMM
    k_uvec<<<2, 1024, 0, s2>>>(Wq, Wk, w);
    k_qk<<<BL / 64, 256, 0, s2>>>(x, bm);
    k_tsort<<<BL / 256, 256, 0, s2>>>();
    k_rankscatter<<<128, 128, 0, s2>>>();
    cudaEventRecord(ev_join, s2);

    // Leg A (default stream): the V projection GEMM
    k_vgemm<<<dim3(BL / 128, DD / 128), 256>>>(x, Wv);

    // join: chunksum needs both g_V (leg A) and g_ksort/g_ord (leg B)
    cudaStreamWaitEvent(0, ev_join, 0);
    k_chunksum<<<BB * 128, 256>>>();
    k_chunkscan<<<BB, 256>>>();
    k_gout<<<NBT, 256, 2 * 33 * 256 * sizeof(float)>>>(out);
}

// round 15
// speedup vs baseline: 1.0563x; 1.0563x over previous
#include <cuda_runtime.h>
#include <cuda_fp16.h>
#include <cstdint>

#define BB 4
#define LL 4096
#define DD 256
#define BL (BB*LL)
#define NB 129          // chunks per batch (128) + overflow bin (t=4096)
#define NBT (BB*NB)

// ---------------- static scratch ----------------
__device__ float g_V[BL*DD];
__device__ float g_uq[DD];
__device__ float g_uk[DD];
__device__ float g_qs[BL];
__device__ float g_ks[BL];
__device__ float g_ksort[BL];
__device__ int   g_ord[BL];
__device__ int   g_t[BL];
__device__ unsigned long long g_tk[BL];   // per-tile sorted packed keys
__device__ int   g_rpart[16*BL];          // per-tile k-rank partials
__device__ int   g_rpartq[16*BL];         // per-tile q-threshold partials
__device__ float g_chE[BB*NB];
__device__ float g_chEV[BB*NB*DD];
__device__ float g_chV[BB*NB*DD];

__device__ __forceinline__ uint32_t fmap(float f) {
    uint32_t u = __float_as_uint(f);
    return ((int)u < 0) ? ~u : (u | 0x80000000u);
}

// ---------------- uq = Wq^T w, uk = Wk^T w ----------------
__global__ void __launch_bounds__(1024) k_uvec(const float* __restrict__ Wq,
                                               const float* __restrict__ Wk,
                                               const float* __restrict__ w) {
    __shared__ float part[4][DD];
    const float* W = (blockIdx.x == 0) ? Wq : Wk;
    int d = threadIdx.x & 255, ec = threadIdx.x >> 8;
    float s = 0.f;
    #pragma unroll 8
    for (int e = ec * 64; e < ec * 64 + 64; e++)
        s = fmaf(W[e * DD + d], w[e], s);
    part[ec][d] = s;
    __syncthreads();
    if (ec == 0) {
        float r = part[0][d] + part[1][d] + part[2][d] + part[3][d];
        if (blockIdx.x == 0) g_uq[d] = r; else g_uk[d] = r;
    }
}

// ---------------- per-row scalar q/k ----------------
__global__ void __launch_bounds__(256) k_qk(const float* __restrict__ x,
                                            const float* __restrict__ bptr) {
    __shared__ float suq[DD], suk[DD];
    suq[threadIdx.x] = g_uq[threadIdx.x];
    suk[threadIdx.x] = g_uk[threadIdx.x];
    __syncthreads();
    int warp = threadIdx.x >> 5, lane = threadIdx.x & 31;
    float bias = bptr[0];
    #pragma unroll
    for (int r = 0; r < 8; r++) {
        int m = blockIdx.x * 64 + warp * 8 + r;
        const float* xr = x + (size_t)m * DD;
        float4 xa = *(const float4*)&xr[lane * 4];
        float4 xb = *(const float4*)&xr[128 + lane * 4];
        int da = lane * 4, db = 128 + lane * 4;
        float sq = xa.x * suq[da] + xa.y * suq[da+1] + xa.z * suq[da+2] + xa.w * suq[da+3]
                 + xb.x * suq[db] + xb.y * suq[db+1] + xb.z * suq[db+2] + xb.w * suq[db+3];
        float sk = xa.x * suk[da] + xa.y * suk[da+1] + xa.z * suk[da+2] + xa.w * suk[da+3]
                 + xb.x * suk[db] + xb.y * suk[db+1] + xb.z * suk[db+2] + xb.w * suk[db+3];
        #pragma unroll
        for (int o = 16; o; o >>= 1) {
            sq += __shfl_down_sync(0xffffffffu, sq, o);
            sk += __shfl_down_sync(0xffffffffu, sk, o);
        }
        if (lane == 0) { g_qs[m] = sq + bias; g_ks[m] = sk; }
    }
}

// ---------------- V = x @ Wv^T : mma.sync fp16 2-pass split ----------------
#define PITCH 36
__device__ __forceinline__ void mma_fp16(float* d, const uint32_t* a, const uint32_t* b) {
    asm volatile("mma.sync.aligned.m16n8k16.row.col.f32.f16.f16.f32 "
        "{%0,%1,%2,%3}, {%4,%5,%6,%7}, {%8,%9}, {%0,%1,%2,%3};"
        : "+f"(d[0]), "+f"(d[1]), "+f"(d[2]), "+f"(d[3])
        : "r"(a[0]), "r"(a[1]), "r"(a[2]), "r"(a[3]), "r"(b[0]), "r"(b[1]));
}

__global__ void __launch_bounds__(256) k_vgemm(const float* __restrict__ x,
                                               const float* __restrict__ Wv) {
    __shared__ __half sAh[128][PITCH];
    __shared__ __half sBh[128][PITCH], sBl[128][PITCH];
    int tid = threadIdx.x, wid = tid >> 5, lane = tid & 31;
    int g = lane >> 2, t4 = lane & 3;
    int wr = wid >> 2, wc = wid & 3;
    int m0 = blockIdx.x * 128, n0 = blockIdx.y * 128;

    float acc[4][4][4];
    #pragma unroll
    for (int mt = 0; mt < 4; mt++)
        #pragma unroll
        for (int nt = 0; nt < 4; nt++)
            #pragma unroll
            for (int e = 0; e < 4; e++) acc[mt][nt][e] = 0.f;

    for (int k0 = 0; k0 < DD; k0 += 32) {
        #pragma unroll
        for (int p = 0; p < 8; p++) {
            int s = p * 256 + tid;
            int row = (s & 1023) >> 3, kq = s & 7;
            if (s < 1024) {
                float4 v = *(const float4*)&x[(size_t)(m0 + row) * DD + k0 + kq * 4];
                __half2 h0 = __floats2half2_rn(v.x, v.y);
                __half2 h1 = __floats2half2_rn(v.z, v.w);
                *(uint2*)&sAh[row][kq * 4] =
                    make_uint2(*(uint32_t*)&h0, *(uint32_t*)&h1);
            } else {
                float4 v = *(const float4*)&Wv[(size_t)(n0 + row) * DD + k0 + kq * 4];
                __half2 h0 = __floats2half2_rn(v.x, v.y);
                __half2 h1 = __floats2half2_rn(v.z, v.w);
                __half2 l0 = __floats2half2_rn(v.x - __low2float(h0),
                                               v.y - __high2float(h0));
                __half2 l1 = __floats2half2_rn(v.z - __low2float(h1),
                                               v.w - __high2float(h1));
                *(uint2*)&sBh[row][kq * 4] =
                    make_uint2(*(uint32_t*)&h0, *(uint32_t*)&h1);
                *(uint2*)&sBl[row][kq * 4] =
                    make_uint2(*(uint32_t*)&l0, *(uint32_t*)&l1);
            }
        }
        __syncthreads();
        #pragma unroll
        for (int ks = 0; ks < 32; ks += 16) {
            uint32_t ah[4][4], bh[4][2], bl[4][2];
            #pragma unroll
            for (int mt = 0; mt < 4; mt++) {
                int rb = wr * 64 + mt * 16;
                int kc = ks + 2 * t4;
                ah[mt][0] = *(uint32_t*)&sAh[rb + g    ][kc];
                ah[mt][1] = *(uint32_t*)&sAh[rb + g + 8][kc];
                ah[mt][2] = *(uint32_t*)&sAh[rb + g    ][kc + 8];
                ah[mt][3] = *(uint32_t*)&sAh[rb + g + 8][kc + 8];
            }
            #pragma unroll
            for (int nt = 0; nt < 4; nt++) {
                int nb = wc * 32 + nt * 8;
                int kc = ks + 2 * t4;
                bh[nt][0] = *(uint32_t*)&sBh[nb + g][kc];
                bh[nt][1] = *(uint32_t*)&sBh[nb + g][kc + 8];
                bl[nt][0] = *(uint32_t*)&sBl[nb + g][kc];
                bl[nt][1] = *(uint32_t*)&sBl[nb + g][kc + 8];
            }
            #pragma unroll
            for (int mt = 0; mt < 4; mt++)
                #pragma unroll
                for (int nt = 0; nt < 4; nt++) {
                    mma_fp16(acc[mt][nt], ah[mt], bh[nt]);
                    mma_fp16(acc[mt][nt], ah[mt], bl[nt]);
                }
        }
        __syncthreads();
    }
    #pragma unroll
    for (int mt = 0; mt < 4; mt++)
        #pragma unroll
        for (int nt = 0; nt < 4; nt++) {
            int m = m0 + wr * 64 + mt * 16 + g;
            int n = n0 + wc * 32 + nt * 8 + 2 * t4;
            *(float2*)&g_V[(size_t)m * DD + n] =
                make_float2(acc[mt][nt][0], acc[mt][nt][1]);
            *(float2*)&g_V[(size_t)(m + 8) * DD + n] =
                make_float2(acc[mt][nt][2], acc[mt][nt][3]);
        }
}

// ---------------- sort 256-key tiles (bitonic, u64 packed keys) ----------------
__global__ void __launch_bounds__(256) k_tsort() {
    __shared__ unsigned long long sk[256];
    int base = blockIdx.x * 256;
    int tid = threadIdx.x;
    int jloc = (base + tid) & (LL - 1);
    sk[tid] = ((unsigned long long)fmap(g_ks[base + tid]) << 12) | (unsigned)jloc;
    __syncthreads();
    for (int k = 2; k <= 256; k <<= 1) {
        for (int j = k >> 1; j > 0; j >>= 1) {
            int ixj = tid ^ j;
            if (ixj > tid) {
                bool asc = ((tid & k) == 0);
                unsigned long long a = sk[tid], c = sk[ixj];
                if (asc ? (a > c) : (a < c)) { sk[tid] = c; sk[ixj] = a; }
            }
            __syncthreads();
        }
    }
    g_tk[base + tid] = sk[tid];
}

// ---------------- exact lower_bound over 256 sorted unique keys (binary) ----------------
__device__ __forceinline__ int lb256(const unsigned long long* st, unsigned long long key) {
    if (st[255] < key) return 256;
    int pos = 0;
    #pragma unroll
    for (int step = 128; step; step >>= 1)
        if (st[pos + step - 1] < key) pos += step;
    return pos;
}

// ---------------- per-tile lower_bounds: 2 queries/thread for ILP ----------------
__global__ void __launch_bounds__(256) k_rank2() {
    __shared__ unsigned long long st[256];
    int tile = blockIdx.x;            // 0..63
    int batch = tile >> 4;
    int tid = threadIdx.x;
    st[tid] = g_tk[tile * 256 + tid];
    int j0 = batch * LL + blockIdx.y * 512 + tid;
    int j1 = j0 + 256;
    unsigned long long kj0 = ((unsigned long long)fmap(g_ks[j0]) << 12)
                           | (unsigned)(j0 & (LL - 1));
    unsigned long long qj0 = ((unsigned long long)fmap(g_qs[j0]) << 12);
    unsigned long long kj1 = ((unsigned long long)fmap(g_ks[j1]) << 12)
                           | (unsigned)(j1 & (LL - 1));
    unsigned long long qj1 = ((unsigned long long)fmap(g_qs[j1]) << 12);
    __syncthreads();
    int part = (tile & 15) * BL;
    g_rpart [part + j0] = lb256(st, kj0);
    g_rpartq[part + j0] = lb256(st, qj0);
    g_rpart [part + j1] = lb256(st, kj1);
    g_rpartq[part + j1] = lb256(st, qj1);
}

// ---------------- final rank: scatter sorted keys + threshold per query ----------------
__global__ void k_ranksum() {
    int j = blockIdx.x * 256 + threadIdx.x;
    int sumk = 0, sumq = 0;
    #pragma unroll
    for (int ic = 0; ic < 16; ic++) {
        sumk += g_rpart [ic * BL + j];
        sumq += g_rpartq[ic * BL + j];
    }
    int b = j >> 12;
    g_ksort[b * LL + sumk] = g_ks[j];
    g_ord[b * LL + sumk]   = j & (LL - 1);
    g_t[j] = sumq;
}

// ---------------- chunk sums (32-element chunks) ----------------
__global__ void __launch_bounds__(256) k_chunksum() {
    int bx = blockIdx.x;
    int b = bx >> 7, c = bx & 127;
    int d = threadIdx.x;
    __shared__ float ev[32];
    __shared__ int   sord[32];
    int base = b * LL + c * 32;
    if (d < 32) {
        float e = expf(-g_ksort[base + d]);
        ev[d] = e;
        sord[d] = g_ord[base + d];
        #pragma unroll
        for (int o = 16; o; o >>= 1) e += __shfl_down_sync(0xffffffffu, e, o);
        if (d == 0) g_chE[b * NB + c] = e;
    }
    __syncthreads();
    float sEV = 0.f, sV = 0.f;
    #pragma unroll 4
    for (int i = 0; i < 32; i++) {
        float v = g_V[(size_t)(b * LL + sord[i]) * DD + d];
        sEV = fmaf(ev[i], v, sEV);
        sV += v;
    }
    g_chEV[(b * NB + c) * DD + d] = sEV;
    g_chV [(b * NB + c) * DD + d] = sV;
}

// ---------------- exclusive scan over chunk sums (+ totals at idx 128) ----------------
__global__ void __launch_bounds__(256) k_chunkscan() {
    int b = blockIdx.x, d = threadIdx.x;
    float runEV = 0.f, runV = 0.f;
    #pragma unroll 8
    for (int c = 0; c < 128; c++) {
        int idx = (b * NB + c) * DD + d;
        float t1 = g_chEV[idx]; g_chEV[idx] = runEV; runEV += t1;
        float t2 = g_chV[idx];  g_chV[idx]  = runV;  runV  += t2;
    }
    g_chEV[(b * NB + 128) * DD + d] = runEV;
    g_chV [(b * NB + 128) * DD + d] = runV;
    if (d == 0) {
        float run = 0.f;
        #pragma unroll 8
        for (int c = 0; c < 128; c++) {
            float t = g_chE[b * NB + c]; g_chE[b * NB + c] = run; run += t;
        }
        g_chE[b * NB + 128] = run;
    }
}

// ---------------- grouped output: one block per (batch, chunk) bin ----------------
__global__ void __launch_bounds__(256) k_gout(float* __restrict__ out) {
    extern __shared__ float dsm[];
    float* pEV = dsm;               // [33][256]
    float* pV  = dsm + 33 * 256;    // [33][256]
    __shared__ float ev[32];
    __shared__ int   sord[32];
    __shared__ float pe[33];
    __shared__ int   slist[4096];
    __shared__ int   scount;
    int gbin = blockIdx.x;
    int b = gbin / NB, c = gbin - b * NB;
    int d = threadIdx.x;
    if (d == 0) scount = 0;
    int csize = (c < 128) ? 32 : 0;
    if (d < 32 && csize) {
        ev[d]   = expf(-g_ksort[b * LL + c * 32 + d]);
        sord[d] = g_ord[b * LL + c * 32 + d];
    }
    __syncthreads();
    // gather this bin's queries from g_t
    #pragma unroll 4
    for (int idx = d; idx < LL; idx += 256) {
        int t = g_t[b * LL + idx];
        if ((t >> 5) == c) slist[atomicAdd(&scount, 1)] = idx;
    }
    __syncthreads();
    int nq = scount;
    if (nq == 0) return;
    // build within-chunk prefixes on top of inter-chunk exclusive base
    pEV[d] = g_chEV[(b * NB + c) * DD + d];
    pV [d] = g_chV [(b * NB + c) * DD + d];
    if (csize) {
        float vr[32];
        #pragma unroll
        for (int i = 0; i < 32; i++)
            vr[i] = g_V[(size_t)(b * LL + sord[i]) * DD + d];
        #pragma unroll
        for (int i = 0; i < 32; i++) {
            pEV[(i + 1) * 256 + d] = fmaf(ev[i], vr[i], pEV[i * 256 + d]);
            pV [(i + 1) * 256 + d] = pV[i * 256 + d] + vr[i];
        }
    }
    if (d == 0) {
        float a = g_chE[b * NB + c];
        pe[0] = a;
        for (int i = 0; i < csize; i++) { a += ev[i]; pe[i + 1] = a; }
    }
    float TVd = g_chV[(b * NB + 128) * DD + d];
    __syncthreads();
    for (int p = 0; p < nq; p++) {
        int ql = slist[p];
        int qi = b * LL + ql;
        int t = g_t[qi];
        int rloc = t - c * 32;
        float E = expf(g_qs[qi]);
        float den = fmaf(E, pe[rloc], (float)(LL - t));
        float num = fmaf(E, pEV[rloc * 256 + d], TVd - pV[rloc * 256 + d]);
        out[(size_t)qi * DD + d] = num / den;
    }
}

// ---------------- launch: fork sort-chain onto a second stream under the GEMM ----------------
extern "C" void kernel_launch(void* const* d_in, const int* in_sizes, int n_in,
                              void* d_out, int out_size) {
    const float* x   = (const float*)d_in[0];
    const float* Wq  = (const float*)d_in[1];
    const float* Wk  = (const float*)d_in[2];
    const float* Wv  = (const float*)d_in[3];
    const float* w   = (const float*)d_in[4];
    const float* bm  = (const float*)d_in[5];
    float* out = (float*)d_out;

    static cudaStream_t s2 = nullptr;
    static cudaEvent_t ev_fork = nullptr, ev_join = nullptr;
    if (!s2) {
        cudaStreamCreateWithFlags(&s2, cudaStreamNonBlocking);
        cudaEventCreateWithFlags(&ev_fork, cudaEventDisableTiming);
        cudaEventCreateWithFlags(&ev_join, cudaEventDisableTiming);
        cudaFuncSetAttribute(k_gout, cudaFuncAttributeMaxDynamicSharedMemorySize,
                             2 * 33 * 256 * (int)sizeof(float));
    }

    // fork
    cudaEventRecord(ev_fork, 0);
    cudaStreamWaitEvent(s2, ev_fork, 0);

    // Leg B (stream s2): scalar/sort/rank chain — latency-bound, hides under GEMM
    k_uvec<<<2, 1024, 0, s2>>>(Wq, Wk, w);
    k_qk<<<BL / 64, 256, 0, s2>>>(x, bm);
    k_tsort<<<BL / 256, 256, 0, s2>>>();
    k_rank2<<<dim3(64, 8), 256, 0, s2>>>();
    k_ranksum<<<BL / 256, 256, 0, s2>>>();
    cudaEventRecord(ev_join, s2);

    // Leg A (default stream): the V projection GEMM
    k_vgemm<<<dim3(BL / 128, DD / 128), 256>>>(x, Wv);

    // join: chunksum needs both g_V (leg A) and g_ksort/g_ord (leg B)
    cudaStreamWaitEvent(0, ev_join, 0);
    k_chunksum<<<BB * 128, 256>>>();
    k_chunkscan<<<BB, 256>>>();
    k_gout<<<NBT, 256, 2 * 33 * 256 * sizeof(float)>>>(out);
}

// round 16
// speedup vs baseline: 1.0866x; 1.0287x over previous
#include <cuda_runtime.h>
#include <cuda_fp16.h>
#include <cstdint>

#define BB 4
#define LL 4096
#define DD 256
#define BL (BB*LL)
#define NB 129          // chunks per batch (128) + overflow bin (t=4096)
#define NBT (BB*NB)

// ---------------- static scratch ----------------
__device__ float g_V[BL*DD];
__device__ float g_uq[DD];
__device__ float g_uk[DD];
__device__ float g_qs[BL];
__device__ float g_ks[BL];
__device__ float g_ksort[BL];
__device__ int   g_ord[BL];
__device__ int   g_t[BL];
__device__ unsigned long long g_tk[BL];   // per-tile sorted packed keys
__device__ float g_chE[BB*NB];
__device__ float g_chEV[BB*NB*DD];
__device__ float g_chV[BB*NB*DD];

__device__ __forceinline__ uint32_t fmap(float f) {
    uint32_t u = __float_as_uint(f);
    return ((int)u < 0) ? ~u : (u | 0x80000000u);
}

// ---------------- uq = Wq^T w, uk = Wk^T w ----------------
__global__ void __launch_bounds__(1024) k_uvec(const float* __restrict__ Wq,
                                               const float* __restrict__ Wk,
                                               const float* __restrict__ w) {
    __shared__ float part[4][DD];
    const float* W = (blockIdx.x == 0) ? Wq : Wk;
    int d = threadIdx.x & 255, ec = threadIdx.x >> 8;
    float s = 0.f;
    #pragma unroll 8
    for (int e = ec * 64; e < ec * 64 + 64; e++)
        s = fmaf(W[e * DD + d], w[e], s);
    part[ec][d] = s;
    __syncthreads();
    if (ec == 0) {
        float r = part[0][d] + part[1][d] + part[2][d] + part[3][d];
        if (blockIdx.x == 0) g_uq[d] = r; else g_uk[d] = r;
    }
}

// ---------------- fused per-row q/k + tile bitonic sort ----------------
// One block = one 256-row tile. 8 warps × 32 rows each, then in-block sort.
__global__ void __launch_bounds__(256) k_qksort(const float* __restrict__ x,
                                                const float* __restrict__ bptr) {
    __shared__ float suq[DD], suk[DD];
    __shared__ unsigned long long skey[256];
    suq[threadIdx.x] = g_uq[threadIdx.x];
    suk[threadIdx.x] = g_uk[threadIdx.x];
    __syncthreads();
    int warp = threadIdx.x >> 5, lane = threadIdx.x & 31;
    int base = blockIdx.x * 256;
    float bias = bptr[0];
    #pragma unroll 4
    for (int r = 0; r < 32; r++) {
        int mloc = warp * 32 + r;
        int m = base + mloc;
        const float* xr = x + (size_t)m * DD;
        float4 xa = *(const float4*)&xr[lane * 4];
        float4 xb = *(const float4*)&xr[128 + lane * 4];
        int da = lane * 4, db = 128 + lane * 4;
        float sq = xa.x * suq[da] + xa.y * suq[da+1] + xa.z * suq[da+2] + xa.w * suq[da+3]
                 + xb.x * suq[db] + xb.y * suq[db+1] + xb.z * suq[db+2] + xb.w * suq[db+3];
        float sk = xa.x * suk[da] + xa.y * suk[da+1] + xa.z * suk[da+2] + xa.w * suk[da+3]
                 + xb.x * suk[db] + xb.y * suk[db+1] + xb.z * suk[db+2] + xb.w * suk[db+3];
        #pragma unroll
        for (int o = 16; o; o >>= 1) {
            sq += __shfl_down_sync(0xffffffffu, sq, o);
            sk += __shfl_down_sync(0xffffffffu, sk, o);
        }
        if (lane == 0) {
            g_qs[m] = sq + bias;
            g_ks[m] = sk;
            skey[mloc] = ((unsigned long long)fmap(sk) << 12)
                       | (unsigned)(m & (LL - 1));
        }
    }
    __syncthreads();
    int tid = threadIdx.x;
    for (int k = 2; k <= 256; k <<= 1) {
        for (int j = k >> 1; j > 0; j >>= 1) {
            int ixj = tid ^ j;
            if (ixj > tid) {
                bool asc = ((tid & k) == 0);
                unsigned long long a = skey[tid], c = skey[ixj];
                if (asc ? (a > c) : (a < c)) { skey[tid] = c; skey[ixj] = a; }
            }
            __syncthreads();
        }
    }
    g_tk[base + tid] = skey[tid];
}

// ---------------- V = x @ Wv^T : mma.sync fp16 2-pass split ----------------
#define PITCH 36
__device__ __forceinline__ void mma_fp16(float* d, const uint32_t* a, const uint32_t* b) {
    asm volatile("mma.sync.aligned.m16n8k16.row.col.f32.f16.f16.f32 "
        "{%0,%1,%2,%3}, {%4,%5,%6,%7}, {%8,%9}, {%0,%1,%2,%3};"
        : "+f"(d[0]), "+f"(d[1]), "+f"(d[2]), "+f"(d[3])
        : "r"(a[0]), "r"(a[1]), "r"(a[2]), "r"(a[3]), "r"(b[0]), "r"(b[1]));
}

__global__ void __launch_bounds__(256) k_vgemm(const float* __restrict__ x,
                                               const float* __restrict__ Wv) {
    __shared__ __half sAh[128][PITCH];
    __shared__ __half sBh[128][PITCH], sBl[128][PITCH];
    int tid = threadIdx.x, wid = tid >> 5, lane = tid & 31;
    int g = lane >> 2, t4 = lane & 3;
    int wr = wid >> 2, wc = wid & 3;
    int m0 = blockIdx.x * 128, n0 = blockIdx.y * 128;

    float acc[4][4][4];
    #pragma unroll
    for (int mt = 0; mt < 4; mt++)
        #pragma unroll
        for (int nt = 0; nt < 4; nt++)
            #pragma unroll
            for (int e = 0; e < 4; e++) acc[mt][nt][e] = 0.f;

    for (int k0 = 0; k0 < DD; k0 += 32) {
        #pragma unroll
        for (int p = 0; p < 8; p++) {
            int s = p * 256 + tid;
            int row = (s & 1023) >> 3, kq = s & 7;
            if (s < 1024) {
                float4 v = *(const float4*)&x[(size_t)(m0 + row) * DD + k0 + kq * 4];
                __half2 h0 = __floats2half2_rn(v.x, v.y);
                __half2 h1 = __floats2half2_rn(v.z, v.w);
                *(uint2*)&sAh[row][kq * 4] =
                    make_uint2(*(uint32_t*)&h0, *(uint32_t*)&h1);
            } else {
                float4 v = *(const float4*)&Wv[(size_t)(n0 + row) * DD + k0 + kq * 4];
                __half2 h0 = __floats2half2_rn(v.x, v.y);
                __half2 h1 = __floats2half2_rn(v.z, v.w);
                __half2 l0 = __floats2half2_rn(v.x - __low2float(h0),
                                               v.y - __high2float(h0));
                __half2 l1 = __floats2half2_rn(v.z - __low2float(h1),
                                               v.w - __high2float(h1));
                *(uint2*)&sBh[row][kq * 4] =
                    make_uint2(*(uint32_t*)&h0, *(uint32_t*)&h1);
                *(uint2*)&sBl[row][kq * 4] =
                    make_uint2(*(uint32_t*)&l0, *(uint32_t*)&l1);
            }
        }
        __syncthreads();
        #pragma unroll
        for (int ks = 0; ks < 32; ks += 16) {
            uint32_t ah[4][4], bh[4][2], bl[4][2];
            #pragma unroll
            for (int mt = 0; mt < 4; mt++) {
                int rb = wr * 64 + mt * 16;
                int kc = ks + 2 * t4;
                ah[mt][0] = *(uint32_t*)&sAh[rb + g    ][kc];
                ah[mt][1] = *(uint32_t*)&sAh[rb + g + 8][kc];
                ah[mt][2] = *(uint32_t*)&sAh[rb + g    ][kc + 8];
                ah[mt][3] = *(uint32_t*)&sAh[rb + g + 8][kc + 8];
            }
            #pragma unroll
            for (int nt = 0; nt < 4; nt++) {
                int nb = wc * 32 + nt * 8;
                int kc = ks + 2 * t4;
                bh[nt][0] = *(uint32_t*)&sBh[nb + g][kc];
                bh[nt][1] = *(uint32_t*)&sBh[nb + g][kc + 8];
                bl[nt][0] = *(uint32_t*)&sBl[nb + g][kc];
                bl[nt][1] = *(uint32_t*)&sBl[nb + g][kc + 8];
            }
            #pragma unroll
            for (int mt = 0; mt < 4; mt++)
                #pragma unroll
                for (int nt = 0; nt < 4; nt++) {
                    mma_fp16(acc[mt][nt], ah[mt], bh[nt]);
                    mma_fp16(acc[mt][nt], ah[mt], bl[nt]);
                }
        }
        __syncthreads();
    }
    #pragma unroll
    for (int mt = 0; mt < 4; mt++)
        #pragma unroll
        for (int nt = 0; nt < 4; nt++) {
            int m = m0 + wr * 64 + mt * 16 + g;
            int n = n0 + wc * 32 + nt * 8 + 2 * t4;
            *(float2*)&g_V[(size_t)m * DD + n] =
                make_float2(acc[mt][nt][0], acc[mt][nt][1]);
            *(float2*)&g_V[(size_t)(m + 8) * DD + n] =
                make_float2(acc[mt][nt][2], acc[mt][nt][3]);
        }
}

// ---------------- exact lower_bound over 256 sorted unique keys (binary) ----------------
__device__ __forceinline__ int lb256(const unsigned long long* st, unsigned long long key) {
    if (st[255] < key) return 256;
    int pos = 0;
    #pragma unroll
    for (int step = 128; step; step >>= 1)
        if (st[pos + step - 1] < key) pos += step;
    return pos;
}

// ---------------- fused rank+threshold+scatter: all 16 tiles resident in smem ----------------
// grid (32, 4): jc, batch. 256 threads; 2 threads per j, 8 tiles each -> ILP 16.
__global__ void __launch_bounds__(256) k_rankall() {
    __shared__ unsigned long long st[4096];   // 32 KB: whole batch's sorted tiles
    __shared__ int pk[256], pq[256];
    int jc = blockIdx.x, b = blockIdx.y;
    int tid = threadIdx.x;
    #pragma unroll
    for (int i = 0; i < 16; i++)
        st[i * 256 + tid] = g_tk[b * LL + i * 256 + tid];
    int th = tid & 127, half = tid >> 7;
    int j = b * LL + jc * 128 + th;
    unsigned long long kj = ((unsigned long long)fmap(g_ks[j]) << 12)
                          | (unsigned)(j & (LL - 1));
    unsigned long long qj = ((unsigned long long)fmap(g_qs[j]) << 12);
    __syncthreads();
    int sumk = 0, sumq = 0;
    const unsigned long long* tb = st + half * 8 * 256;
    #pragma unroll
    for (int t = 0; t < 8; t++) {
        sumk += lb256(tb + t * 256, kj);
        sumq += lb256(tb + t * 256, qj);
    }
    pk[tid] = sumk;
    pq[tid] = sumq;
    __syncthreads();
    if (tid < 128) {
        int SK = pk[tid] + pk[tid + 128];
        int SQ = pq[tid] + pq[tid + 128];
        g_ksort[b * LL + SK] = g_ks[j];
        g_ord  [b * LL + SK] = j & (LL - 1);
        g_t[j] = SQ;
    }
}

// ---------------- chunk sums (32-element chunks) ----------------
__global__ void __launch_bounds__(256) k_chunksum() {
    int bx = blockIdx.x;
    int b = bx >> 7, c = bx & 127;
    int d = threadIdx.x;
    __shared__ float ev[32];
    __shared__ int   sord[32];
    int base = b * LL + c * 32;
    if (d < 32) {
        float e = expf(-g_ksort[base + d]);
        ev[d] = e;
        sord[d] = g_ord[base + d];
        #pragma unroll
        for (int o = 16; o; o >>= 1) e += __shfl_down_sync(0xffffffffu, e, o);
        if (d == 0) g_chE[b * NB + c] = e;
    }
    __syncthreads();
    float sEV = 0.f, sV = 0.f;
    #pragma unroll 4
    for (int i = 0; i < 32; i++) {
        float v = g_V[(size_t)(b * LL + sord[i]) * DD + d];
        sEV = fmaf(ev[i], v, sEV);
        sV += v;
    }
    g_chEV[(b * NB + c) * DD + d] = sEV;
    g_chV [(b * NB + c) * DD + d] = sV;
}

// ---------------- exclusive scan over chunk sums (+ totals at idx 128) ----------------
__global__ void __launch_bounds__(256) k_chunkscan() {
    int b = blockIdx.x, d = threadIdx.x;
    float runEV = 0.f, runV = 0.f;
    #pragma unroll 8
    for (int c = 0; c < 128; c++) {
        int idx = (b * NB + c) * DD + d;
        float t1 = g_chEV[idx]; g_chEV[idx] = runEV; runEV += t1;
        float t2 = g_chV[idx];  g_chV[idx]  = runV;  runV  += t2;
    }
    g_chEV[(b * NB + 128) * DD + d] = runEV;
    g_chV [(b * NB + 128) * DD + d] = runV;
    if (d == 0) {
        float run = 0.f;
        #pragma unroll 8
        for (int c = 0; c < 128; c++) {
            float t = g_chE[b * NB + c]; g_chE[b * NB + c] = run; run += t;
        }
        g_chE[b * NB + 128] = run;
    }
}

// ---------------- grouped output: one block per (batch, chunk) bin ----------------
__global__ void __launch_bounds__(256) k_gout(float* __restrict__ out) {
    extern __shared__ float dsm[];
    float* pEV = dsm;               // [33][256]
    float* pV  = dsm + 33 * 256;    // [33][256]
    __shared__ float ev[32];
    __shared__ int   sord[32];
    __shared__ float pe[33];
    __shared__ int   slist[4096];
    __shared__ int   scount;
    int gbin = blockIdx.x;
    int b = gbin / NB, c = gbin - b * NB;
    int d = threadIdx.x;
    if (d == 0) scount = 0;
    int csize = (c < 128) ? 32 : 0;
    if (d < 32 && csize) {
        ev[d]   = expf(-g_ksort[b * LL + c * 32 + d]);
        sord[d] = g_ord[b * LL + c * 32 + d];
    }
    __syncthreads();
    // gather this bin's queries from g_t
    #pragma unroll 4
    for (int idx = d; idx < LL; idx += 256) {
        int t = g_t[b * LL + idx];
        if ((t >> 5) == c) slist[atomicAdd(&scount, 1)] = idx;
    }
    __syncthreads();
    int nq = scount;
    if (nq == 0) return;
    // build within-chunk prefixes on top of inter-chunk exclusive base
    pEV[d] = g_chEV[(b * NB + c) * DD + d];
    pV [d] = g_chV [(b * NB + c) * DD + d];
    if (csize) {
        float vr[32];
        #pragma unroll
        for (int i = 0; i < 32; i++)
            vr[i] = g_V[(size_t)(b * LL + sord[i]) * DD + d];
        #pragma unroll
        for (int i = 0; i < 32; i++) {
            pEV[(i + 1) * 256 + d] = fmaf(ev[i], vr[i], pEV[i * 256 + d]);
            pV [(i + 1) * 256 + d] = pV[i * 256 + d] + vr[i];
        }
    }
    if (d == 0) {
        float a = g_chE[b * NB + c];
        pe[0] = a;
        for (int i = 0; i < csize; i++) { a += ev[i]; pe[i + 1] = a; }
    }
    float TVd = g_chV[(b * NB + 128) * DD + d];
    __syncthreads();
    for (int p = 0; p < nq; p++) {
        int ql = slist[p];
        int qi = b * LL + ql;
        int t = g_t[qi];
        int rloc = t - c * 32;
        float E = expf(g_qs[qi]);
        float den = fmaf(E, pe[rloc], (float)(LL - t));
        float num = fmaf(E, pEV[rloc * 256 + d], TVd - pV[rloc * 256 + d]);
        out[(size_t)qi * DD + d] = num / den;
    }
}

// ---------------- launch: fork sort-chain onto a second stream under the GEMM ----------------
extern "C" void kernel_launch(void* const* d_in, const int* in_sizes, int n_in,
                              void* d_out, int out_size) {
    const float* x   = (const float*)d_in[0];
    const float* Wq  = (const float*)d_in[1];
    const float* Wk  = (const float*)d_in[2];
    const float* Wv  = (const float*)d_in[3];
    const float* w   = (const float*)d_in[4];
    const float* bm  = (const float*)d_in[5];
    float* out = (float*)d_out;

    static cudaStream_t s2 = nullptr;
    static cudaEvent_t ev_fork = nullptr, ev_join = nullptr;
    if (!s2) {
        cudaStreamCreateWithFlags(&s2, cudaStreamNonBlocking);
        cudaEventCreateWithFlags(&ev_fork, cudaEventDisableTiming);
        cudaEventCreateWithFlags(&ev_join, cudaEventDisableTiming);
        cudaFuncSetAttribute(k_gout, cudaFuncAttributeMaxDynamicSharedMemorySize,
                             2 * 33 * 256 * (int)sizeof(float));
    }

    // fork
    cudaEventRecord(ev_fork, 0);
    cudaStreamWaitEvent(s2, ev_fork, 0);

    // Leg B (stream s2): scalar/sort/rank chain — latency-bound, hides under GEMM
    k_uvec<<<2, 1024, 0, s2>>>(Wq, Wk, w);
    k_qksort<<<BL / 256, 256, 0, s2>>>(x, bm);
    k_rankall<<<dim3(32, BB), 256, 0, s2>>>();
    cudaEventRecord(ev_join, s2);

    // Leg A (default stream): the V projection GEMM
    k_vgemm<<<dim3(BL / 128, DD / 128), 256>>>(x, Wv);

    // join: chunksum needs both g_V (leg A) and g_ksort/g_ord (leg B)
    cudaStreamWaitEvent(0, ev_join, 0);
    k_chunksum<<<BB * 128, 256>>>();
    k_chunkscan<<<BB, 256>>>();
    k_gout<<<NBT, 256, 2 * 33 * 256 * sizeof(float)>>>(out);
}